// round 2
// baseline (speedup 1.0000x reference)
#include <cuda_runtime.h>
#include <cuda_bf16.h>
#include <cooperative_groups.h>

namespace cg = cooperative_groups;

// Problem constants
#define NB     32
#define NZ     100
#define STATE  20
#define HIDN   128
#define HH     32
#define WW     32
#define STEPS  64
#define THRESH 0.1f

#define PIX    1024                       // 32*32
#define IMG_SZ (STATE*PIX)                // 20480 floats per image
#define STATE_SZ (NB*IMG_SZ)
#define SPR    4                          // strips per row (8 px each)
#define NSTRIP (SPR*HH)                   // 128 strips per image

// ---------------- persistent device scratch ----------------
__device__ __align__(16) float g_S[STATE_SZ];
__device__ __align__(16) float g_T[STATE_SZ];
__device__ unsigned char      g_P  [NB*PIX];     // pre-mask per pixel
__device__ unsigned char      g_HOT[NB*NSTRIP];  // strip hot this step
__device__ unsigned char      g_NZ [NB*NSTRIP];  // strip has nonzero state

// ---------------- shared memory layout (floats) ----------------
#define OFF_WP   0                        // [3][60][128]  perceive wt, kx-major
#define OFF_WU1  23040                    // [128k][128h]  up1 wt transposed
#define OFF_WU2  39424                    // [20][128]     up2 wt
#define OFF_BP   41984                    // [128]
#define OFF_BU1  42112                    // [128]
#define OFF_BU2  42240                    // [32]
#define OFF_G0   42272                    // per-group scratch, 2816 floats each
#define GRP_SZ   2816
//   group scratch:   patch [20][3][12] = 720
#define GOF_PERC 720                      //  s_perc [128][8] = 1024
#define GOF_H2   1744                     //  s_h2T  [8][132] = 1056 (padded)
#define OFF_FLAG 47904                    // 8 ints of flags
#define SMEM_FLOATS 47912
#define SMEM_BYTES  (SMEM_FLOATS*4)

__device__ __forceinline__ void group_bar(int g) {
    asm volatile("bar.sync %0, 128;" :: "r"(1 + g) : "memory");
}

__global__ void __launch_bounds__(256, 1) __cluster_dims__(4, 1, 1)
k_main(const float* __restrict__ z,
       const float* __restrict__ w1, const float* __restrict__ b1,
       const float* __restrict__ w2, const float* __restrict__ b2,
       const float* __restrict__ wp, const float* __restrict__ bp,
       const float* __restrict__ wu1, const float* __restrict__ bu1,
       const float* __restrict__ wu2, const float* __restrict__ bu2,
       float* __restrict__ out)
{
    extern __shared__ float sm[];
    cg::cluster_group cluster = cg::this_cluster();

    const int t    = threadIdx.x;           // 0..255
    const int n    = blockIdx.x >> 2;       // image
    const int rank = blockIdx.x & 3;        // CTA within cluster
    const int g    = t >> 7;                // group (0/1) within CTA
    const int tl   = t & 127;               // thread within group
    const int lane = t & 31;
    const int gid  = rank*2 + g;            // group id within image: 0..7

    float* __restrict__ Sn = g_S + n*IMG_SZ;
    float* __restrict__ Tn = g_T + n*IMG_SZ;
    unsigned char* __restrict__ Pn   = g_P   + n*PIX;
    unsigned char* __restrict__ HOTn = g_HOT + n*NSTRIP;
    unsigned char* __restrict__ NZn  = g_NZ  + n*NSTRIP;

    float* swp  = sm + OFF_WP;
    float* swu1 = sm + OFF_WU1;
    float* swu2 = sm + OFF_WU2;
    float* sbp  = sm + OFF_BP;
    float* sbu1 = sm + OFF_BU1;
    float* sbu2 = sm + OFF_BU2;
    float* gbase  = sm + OFF_G0 + g*GRP_SZ;
    float* patch  = gbase;                   // [20][3][12]
    float* sperc  = gbase + GOF_PERC;        // [128][8]
    float* sh2T   = gbase + GOF_H2;          // [8][132]
    int*   sflag  = (int*)(sm + OFF_FLAG);   // [2 groups][2 parity]

    // ---- load + repack weights into SMEM (per CTA, once) ----
    for (int i = t; i < 128*180; i += 256) {
        int h = i / 180, k = i % 180;
        int kx = k % 3, cr = k / 3;
        swp[(kx*60 + cr)*128 + h] = wp[i];
    }
    for (int i = t; i < 128*128; i += 256) {
        int h = i >> 7, k = i & 127;
        swu1[k*128 + h] = wu1[i];
    }
    for (int i = t; i < 20*128; i += 256) swu2[i] = wu2[i];
    if (t < 128) { sbp[t] = bp[t]; sbu1[t] = bu1[t]; }
    if (t < 20)  sbu2[t] = bu2[t];

    // ---- zero this CTA's quarter of the image state ----
    for (int i = t; i < IMG_SZ/4; i += 256) Sn[rank*(IMG_SZ/4) + i] = 0.f;
    __syncthreads();
    cluster.sync();

    // ---- init MLP + flags (rank 0 only) ----
    if (rank == 0) {
        float* zz = gbase;            // reuse scratch (>=150 floats available)
        float* hh = gbase + 128;
        if (t < NZ) zz[t] = z[n*NZ + t];
        __syncthreads();
        if (t < 50) {
            float a = b1[t];
            for (int j = 0; j < NZ; j++) a = fmaf(w1[t*NZ + j], zz[j], a);
            hh[t] = fmaxf(a, 0.f);
        }
        __syncthreads();
        const int ctr = 16*WW + 16;
        if (t < STATE-1) {
            float a = b2[t];
            for (int j = 0; j < 50; j++) a = fmaf(w2[t*50 + j], hh[j], a);
            Sn[(1+t)*PIX + ctr] = a;
        }
        if (t == STATE-1) Sn[0*PIX + ctr] = 0.5f;
        if (t < NSTRIP) NZn[t] = (t == (16*SPR + 2)) ? 1 : 0;  // center strip
        __syncthreads();
    }
    cluster.sync();

    // =================== 64 steps ===================
    for (int step = 0; step < STEPS; step++) {

        // ---------- phase 1: per-strip hot test + update -> T, pre-mask ----------
        for (int it = 0; it < 16; it++) {
            const int idx = it*8 + gid;          // strip id 0..127
            const int y   = idx >> 2;
            const int x0  = (idx & 3) * 8;

            // dead test by warp 0 of the group (5x12 ch0 window > THRESH)
            if ((tl >> 5) == 0) {
                int h1 = 0;
                #pragma unroll
                for (int v = lane; v < 60; v += 32) {
                    int r = v / 12, c = v % 12;
                    int yy = y - 2 + r, xx = x0 - 2 + c;
                    if ((unsigned)yy < (unsigned)HH && (unsigned)xx < (unsigned)WW)
                        if (Sn[yy*WW + xx] > THRESH) h1 = 1;
                }
                h1 = __any_sync(0xffffffffu, h1);
                if (lane == 0) sflag[g*2 + (it & 1)] = h1;
            }
            group_bar(g);
            int hotv = sflag[g*2 + (it & 1)];
            if (tl == 0) HOTn[idx] = (unsigned char)hotv;
            if (!hotv) continue;

            // load patch [20][3][12]
            for (int i = tl; i < STATE*3*12; i += 128) {
                int c = i / 36, rem = i - c*36, r = rem / 12, col = rem - r*12;
                int yy = y - 1 + r, xx = x0 - 1 + col;
                float v = 0.f;
                if (col < 10 && (unsigned)yy < (unsigned)HH && (unsigned)xx < (unsigned)WW)
                    v = Sn[c*PIX + yy*WW + xx];
                patch[(c*3 + r)*12 + col] = v;
            }
            group_bar(g);

            // pre-mask for 8 strip pixels
            if (tl < 8) {
                float m = 0.f;
                #pragma unroll
                for (int r = 0; r < 3; r++)
                    #pragma unroll
                    for (int cc = 0; cc < 3; cc++)
                        m = fmaxf(m, patch[r*12 + tl + cc]);
                Pn[y*WW + x0 + tl] = (m > THRESH) ? 1 : 0;
            }

            // perceive: 3x3 conv 20->128; thread = hid channel, 8 px
            float acc[8];
            {
                float b = sbp[tl];
                #pragma unroll
                for (int p = 0; p < 8; p++) acc[p] = b;
            }
            #pragma unroll 4
            for (int cr = 0; cr < 60; cr++) {
                const float4 a4 = *(const float4*)&patch[cr*12 + 0];
                const float4 b4 = *(const float4*)&patch[cr*12 + 4];
                const float4 d4 = *(const float4*)&patch[cr*12 + 8];
                float rv[12] = {a4.x,a4.y,a4.z,a4.w, b4.x,b4.y,b4.z,b4.w, d4.x,d4.y,d4.z,d4.w};
                #pragma unroll
                for (int kx = 0; kx < 3; kx++) {
                    float w = swp[(kx*60 + cr)*128 + tl];
                    #pragma unroll
                    for (int p = 0; p < 8; p++)
                        acc[p] = fmaf(w, rv[p + kx], acc[p]);
                }
            }
            #pragma unroll
            for (int p = 0; p < 8; p++) sperc[tl*8 + p] = acc[p];
            group_bar(g);

            // up1: 1x1 128->128 + relu; result transposed sh2T[p][132]
            float acc2[8];
            {
                float b = sbu1[tl];
                #pragma unroll
                for (int p = 0; p < 8; p++) acc2[p] = b;
            }
            #pragma unroll 4
            for (int k = 0; k < 128; k++) {
                const float4 va = *(const float4*)&sperc[k*8 + 0];
                const float4 vb = *(const float4*)&sperc[k*8 + 4];
                float w = swu1[k*128 + tl];
                acc2[0] = fmaf(w, va.x, acc2[0]);
                acc2[1] = fmaf(w, va.y, acc2[1]);
                acc2[2] = fmaf(w, va.z, acc2[2]);
                acc2[3] = fmaf(w, va.w, acc2[3]);
                acc2[4] = fmaf(w, vb.x, acc2[4]);
                acc2[5] = fmaf(w, vb.y, acc2[5]);
                acc2[6] = fmaf(w, vb.z, acc2[6]);
                acc2[7] = fmaf(w, vb.w, acc2[7]);
            }
            #pragma unroll
            for (int p = 0; p < 8; p++) sh2T[p*132 + tl] = fmaxf(acc2[p], 0.f);
            group_bar(g);

            // up2: 1x1 128->20, T = S + upd (160 outputs over 128 threads)
            {
                int c = tl >> 3, p = tl & 7;
                float a = sbu2[c];
                #pragma unroll 8
                for (int k4 = 0; k4 < 32; k4++) {
                    const float4 h4 = *(const float4*)&sh2T[p*132 + k4*4];
                    const float4 w4 = *(const float4*)&swu2[c*128 + k4*4];
                    a = fmaf(w4.x, h4.x, a);
                    a = fmaf(w4.y, h4.y, a);
                    a = fmaf(w4.z, h4.z, a);
                    a = fmaf(w4.w, h4.w, a);
                }
                Tn[c*PIX + y*WW + x0 + p] = patch[(c*3+1)*12 + p+1] + a;
            }
            if (tl < 32) {
                int i2 = tl + 128;
                int c = i2 >> 3, p = i2 & 7;
                float a = sbu2[c];
                #pragma unroll 8
                for (int k4 = 0; k4 < 32; k4++) {
                    const float4 h4 = *(const float4*)&sh2T[p*132 + k4*4];
                    const float4 w4 = *(const float4*)&swu2[c*128 + k4*4];
                    a = fmaf(w4.x, h4.x, a);
                    a = fmaf(w4.y, h4.y, a);
                    a = fmaf(w4.z, h4.z, a);
                    a = fmaf(w4.w, h4.w, a);
                }
                Tn[c*PIX + y*WW + x0 + p] = patch[(c*3+1)*12 + p+1] + a;
            }
            group_bar(g);   // protect patch/sperc/sh2T reuse next iteration
        }

        cluster.sync();

        // ---------- phase 2: post maxpool + masking -> S ----------
        {
            const int j  = t >> 3;             // row 0..31
            const int p  = t & 7;
            const int y  = j;
            const int x  = rank*8 + p;
            const int idx = y*SPR + rank;      // strip: column sx=rank
            const int px  = y*WW + x;

            unsigned char hot = HOTn[idx];
            unsigned char nz  = NZn[idx];
            bool myalive = false;
            if (hot && Pn[px]) {
                float m = 0.f;
                #pragma unroll
                for (int dy = -1; dy <= 1; dy++) {
                    int yy = y + dy;
                    if ((unsigned)yy >= (unsigned)HH) continue;
                    #pragma unroll
                    for (int dx = -1; dx <= 1; dx++) {
                        int xx = x + dx;
                        if ((unsigned)xx >= (unsigned)WW) continue;
                        m = fmaxf(m, Tn[yy*WW + xx]);
                    }
                }
                myalive = m > THRESH;
            }
            unsigned bal = __ballot_sync(0xffffffffu, myalive);
            if (hot) {
                if (myalive) {
                    #pragma unroll
                    for (int c = 0; c < STATE; c++) Sn[c*PIX + px] = Tn[c*PIX + px];
                } else {
                    #pragma unroll
                    for (int c = 0; c < STATE; c++) Sn[c*PIX + px] = 0.f;
                }
                if (p == 0)
                    NZn[idx] = ((bal >> (lane & 24)) & 0xFF) ? 1 : 0;
            } else if (nz) {
                #pragma unroll
                for (int c = 0; c < STATE; c++) Sn[c*PIX + px] = 0.f;
                if (p == 0) NZn[idx] = 0;
            }
        }

        cluster.sync();
    }

    // ---- extract ch0 ----
    for (int i = t; i < PIX/4; i += 256)
        out[n*PIX + rank*(PIX/4) + i] = Sn[rank*(PIX/4) + i];
}

extern "C" void kernel_launch(void* const* d_in, const int* in_sizes, int n_in,
                              void* d_out, int out_size)
{
    const float* z   = (const float*)d_in[0];
    const float* w1  = (const float*)d_in[1];
    const float* b1  = (const float*)d_in[2];
    const float* w2  = (const float*)d_in[3];
    const float* b2  = (const float*)d_in[4];
    const float* wp  = (const float*)d_in[5];
    const float* bp  = (const float*)d_in[6];
    const float* wu1 = (const float*)d_in[7];
    const float* bu1 = (const float*)d_in[8];
    const float* wu2 = (const float*)d_in[9];
    const float* bu2 = (const float*)d_in[10];
    float* out = (float*)d_out;

    static int attr_done = 0;
    if (!attr_done) {
        cudaFuncSetAttribute(k_main, cudaFuncAttributeMaxDynamicSharedMemorySize, SMEM_BYTES);
        attr_done = 1;
    }
    k_main<<<NB*4, 256, SMEM_BYTES>>>(z, w1, b1, w2, b2, wp, bp, wu1, bu1, wu2, bu2, out);
}

// round 3
// speedup vs baseline: 1.1150x; 1.1150x over previous
#include <cuda_runtime.h>
#include <cuda_bf16.h>

// Problem constants
#define NB     32
#define NZ     100
#define STATE  20
#define HIDN   128
#define HH     32
#define WW     32
#define STEPS  64
#define THRESH 0.1f

#define PIX    1024
#define IMG_SZ (STATE*PIX)
#define STATE_SZ (NB*IMG_SZ)
#define SPR    4
#define NSTRIP (SPR*HH)                  // 128 strips per image
#define TOTSTRIP (NB*NSTRIP)             // 4096

// ---------------- persistent device scratch ----------------
__device__ __align__(16) float g_S[STATE_SZ];
__device__ __align__(16) float g_T[STATE_SZ];
__device__ unsigned char      g_P  [NB*PIX];      // pre-mask per pixel
__device__ unsigned char      g_HOT[TOTSTRIP];    // strip hot (candidate) this step
__device__ unsigned char      g_NZ [TOTSTRIP];    // strip has alive pixel (post-step)
__device__ int                g_cnt[STEPS];       // worklist counts
__device__ int                g_wl [TOTSTRIP];    // worklist (strip ids)
// packed weights
__device__ __align__(16) float g_wp_pad [60*128*4];   // [cr][hid][4] (3 used)
__device__ __align__(16) float g_wu1T   [128*128];    // [k][hid]

// ---------------- f32x2 helpers ----------------
__device__ __forceinline__ unsigned long long pack2(float v) {
    unsigned long long r;
    asm("mov.b64 %0, {%1, %1};" : "=l"(r) : "f"(v));
    return r;
}
__device__ __forceinline__ void fma2(unsigned long long& d,
                                     unsigned long long a, unsigned long long b) {
    asm("fma.rn.f32x2 %0, %1, %2, %0;" : "+l"(d) : "l"(a), "l"(b));
}
__device__ __forceinline__ float2 unpack2(unsigned long long v) {
    float lo, hi;
    asm("mov.b64 {%0, %1}, %2;" : "=f"(lo), "=f"(hi) : "l"(v));
    return make_float2(lo, hi);
}

// ---------------- weight repack ----------------
__global__ void k_pack(const float* __restrict__ wp, const float* __restrict__ wu1)
{
    int i = blockIdx.x*256 + threadIdx.x;
    if (i < 128*180) {
        int h = i / 180, k = i % 180;            // k = c*9 + r*3 + kx
        g_wp_pad[(k/3)*512 + h*4 + (k%3)] = wp[i];
    }
    if (i < 128*128) {
        int h = i >> 7, k = i & 127;
        g_wu1T[k*128 + h] = wu1[i];
    }
}

// ---------------- zero state + bookkeeping ----------------
__global__ void k_zero()
{
    int i = blockIdx.x*256 + threadIdx.x;
    if (i < STATE_SZ) g_S[i] = 0.f;
    if (i < TOTSTRIP) g_NZ[i] = 0;
    if (i < STEPS)    g_cnt[i] = 0;
}

// ---------------- init MLP ----------------
__global__ void k_init(const float* __restrict__ z,
                       const float* __restrict__ w1, const float* __restrict__ b1,
                       const float* __restrict__ w2, const float* __restrict__ b2)
{
    int n = blockIdx.x;
    int t = threadIdx.x;  // 128
    __shared__ float zz[NZ];
    __shared__ float h[50];
    if (t < NZ) zz[t] = z[n*NZ + t];
    __syncthreads();
    if (t < 50) {
        float a = b1[t];
        #pragma unroll 4
        for (int j = 0; j < NZ; j++) a = fmaf(w1[t*NZ + j], zz[j], a);
        h[t] = fmaxf(a, 0.f);
    }
    __syncthreads();
    const int ctr = 16*WW + 16;
    if (t < STATE-1) {
        float a = b2[t];
        #pragma unroll 5
        for (int j = 0; j < 50; j++) a = fmaf(w2[t*50 + j], h[j], a);
        g_S[n*IMG_SZ + (1+t)*PIX + ctr] = a;
    }
    if (t == STATE-1) {
        g_S[n*IMG_SZ + ctr] = 0.5f;                // ch0 center
        g_NZ[n*NSTRIP + 16*SPR + 2] = 1;           // center strip alive
    }
}

// ---------------- worklist build: dilate NZ by 5 rows x 3 strip-cols ----------------
__global__ void k_build(int step)
{
    int e = blockIdx.x*256 + threadIdx.x;          // 0..4095
    if (e >= TOTSTRIP) return;
    int n = e >> 7, idx = e & 127, y = idx >> 2, sx = idx & 3;
    const unsigned char* A = g_NZ + n*NSTRIP;
    int cand = 0;
    #pragma unroll
    for (int dy = -2; dy <= 2; dy++) {
        int yy = y + dy;
        if ((unsigned)yy >= (unsigned)HH) continue;
        #pragma unroll
        for (int ds = -1; ds <= 1; ds++) {
            int ss = sx + ds;
            if ((unsigned)ss >= (unsigned)SPR) continue;
            cand |= A[yy*SPR + ss];
        }
    }
    g_HOT[e] = (unsigned char)(cand ? 1 : 0);
    // warp-aggregated worklist append
    unsigned bal = __ballot_sync(0xffffffffu, cand != 0);
    if (cand) {
        int lane = threadIdx.x & 31;
        int rank = __popc(bal & ((1u << lane) - 1u));
        int base = 0;
        if (rank == 0) base = atomicAdd(&g_cnt[step], __popc(bal));
        base = __shfl_sync(0xffffffffu, base, __ffs(bal) - 1);
        g_wl[base + rank] = e;
    }
}

// ---------------- step kernel 1: worklist strips -> T + pre-mask ----------------
__global__ void __launch_bounds__(128)
k_step1(int step,
        const float* __restrict__ bp,
        const float* __restrict__ bu1,
        const float* __restrict__ wu2, const float* __restrict__ bu2)
{
    __shared__ __align__(16) float patchA[60*12];
    __shared__ __align__(16) float patchB[60*12];
    __shared__ __align__(16) float sperc[HIDN*8];     // [hid][8]
    __shared__ __align__(16) float sh2T[8*132];       // [p][132]

    const int t = threadIdx.x;
    const int cnt = g_cnt[step];

    for (int wi = blockIdx.x; wi < cnt; wi += gridDim.x) {
        const int e   = g_wl[wi];
        const int n   = e >> 7;
        const int idx = e & 127;
        const int y   = idx >> 2;
        const int x0  = (idx & 3) * 8;

        const float* __restrict__ Sn = g_S + n*IMG_SZ;
        float* __restrict__ Tn = g_T + n*IMG_SZ;

        // ---- load patch [20][3][12] plus shifted copy ----
        for (int i = t; i < 60*12; i += 128) {
            int row = i / 12, col = i - row*12;      // row = c*3 + r
            int c = row / 3, r = row - c*3;
            int yy = y - 1 + r, xx = x0 - 1 + col;
            float v = 0.f;
            if (col < 10 && (unsigned)yy < (unsigned)HH && (unsigned)xx < (unsigned)WW)
                v = Sn[c*PIX + yy*WW + xx];
            patchA[i] = v;
            if (col >= 1) patchB[i - 1] = v;
            else          patchB[row*12 + 11] = 0.f;
        }
        __syncthreads();

        // ---- pre-mask for 8 strip pixels ----
        if (t < 8) {
            float m = 0.f;
            #pragma unroll
            for (int r = 0; r < 3; r++)
                #pragma unroll
                for (int cc = 0; cc < 3; cc++)
                    m = fmaxf(m, patchA[r*12 + t + cc]);
            g_P[n*PIX + y*WW + x0 + t] = (m > THRESH) ? 1 : 0;
        }

        // ---- perceive: 3x3 conv 20->128, f32x2 over pixel pairs ----
        unsigned long long acc[4];
        {
            unsigned long long b2v = pack2(__ldg(&bp[t]));
            acc[0] = b2v; acc[1] = b2v; acc[2] = b2v; acc[3] = b2v;
        }
        #pragma unroll 2
        for (int cr = 0; cr < 60; cr++) {
            const ulonglong2 pa0 = *(const ulonglong2*)&patchA[cr*12 + 0]; // (0,1)(2,3)
            const ulonglong2 pa1 = *(const ulonglong2*)&patchA[cr*12 + 4]; // (4,5)(6,7)
            const unsigned long long d8 = *(const unsigned long long*)&patchA[cr*12 + 8]; // (8,9)
            const ulonglong2 pb0 = *(const ulonglong2*)&patchB[cr*12 + 0]; // (1,2)(3,4)
            const ulonglong2 pb1 = *(const ulonglong2*)&patchB[cr*12 + 4]; // (5,6)(7,8)
            const float4 w4 = __ldg((const float4*)&g_wp_pad[(cr*128 + t)*4]);
            const unsigned long long W0 = pack2(w4.x);
            const unsigned long long W1 = pack2(w4.y);
            const unsigned long long W2 = pack2(w4.z);
            fma2(acc[0], W0, pa0.x); fma2(acc[1], W0, pa0.y);
            fma2(acc[2], W0, pa1.x); fma2(acc[3], W0, pa1.y);
            fma2(acc[0], W1, pb0.x); fma2(acc[1], W1, pb0.y);
            fma2(acc[2], W1, pb1.x); fma2(acc[3], W1, pb1.y);
            fma2(acc[0], W2, pa0.y); fma2(acc[1], W2, pa1.x);
            fma2(acc[2], W2, pa1.y); fma2(acc[3], W2, d8);
        }
        {
            unsigned long long* sp = (unsigned long long*)sperc;
            sp[t*4 + 0] = acc[0]; sp[t*4 + 1] = acc[1];
            sp[t*4 + 2] = acc[2]; sp[t*4 + 3] = acc[3];
        }
        __syncthreads();

        // ---- up1: 1x1 128->128 + relu, f32x2 over pixel pairs ----
        unsigned long long acc2[4];
        {
            unsigned long long b2v = pack2(__ldg(&bu1[t]));
            acc2[0] = b2v; acc2[1] = b2v; acc2[2] = b2v; acc2[3] = b2v;
        }
        #pragma unroll 4
        for (int k = 0; k < 128; k++) {
            const ulonglong2 v0 = *(const ulonglong2*)&sperc[k*8 + 0];
            const ulonglong2 v1 = *(const ulonglong2*)&sperc[k*8 + 4];
            const unsigned long long W = pack2(__ldg(&g_wu1T[k*128 + t]));
            fma2(acc2[0], W, v0.x); fma2(acc2[1], W, v0.y);
            fma2(acc2[2], W, v1.x); fma2(acc2[3], W, v1.y);
        }
        #pragma unroll
        for (int j = 0; j < 4; j++) {
            float2 v = unpack2(acc2[j]);
            sh2T[(2*j+0)*132 + t] = fmaxf(v.x, 0.f);
            sh2T[(2*j+1)*132 + t] = fmaxf(v.y, 0.f);
        }
        __syncthreads();

        // ---- up2: 1x1 128->20 (160 outputs over 128 threads, 2 rounds) ----
        #pragma unroll
        for (int round = 0; round < 2; round++) {
            int i2 = t + round*128;
            if (i2 < 160) {
                int c = i2 >> 3, p = i2 & 7;
                unsigned long long A0 = 0ull, A1 = 0ull;  // packed zeros
                const ulonglong2* hv = (const ulonglong2*)&sh2T[p*132];
                const ulonglong2* wv = (const ulonglong2*)&wu2[c*128];
                #pragma unroll 8
                for (int k4 = 0; k4 < 32; k4++) {
                    const ulonglong2 h2 = hv[k4];
                    const ulonglong2 w2 = __ldg(&wv[k4]);
                    fma2(A0, w2.x, h2.x);
                    fma2(A1, w2.y, h2.y);
                }
                float2 s0 = unpack2(A0), s1 = unpack2(A1);
                float a = __ldg(&bu2[c]) + ((s0.x + s0.y) + (s1.x + s1.y));
                Tn[c*PIX + y*WW + x0 + p] = patchA[(c*3+1)*12 + p + 1] + a;
            }
        }
        __syncthreads();   // protect smem reuse across worklist iterations
    }
}

// ---------------- step kernel 2: post maxpool + masking -> S, NZ ----------------
__global__ void __launch_bounds__(256)
k_step2()
{
    int g = blockIdx.x*256 + threadIdx.x;     // 0..32767
    int n = g >> 10, rem = g & 1023;
    int y = rem >> 5, x = rem & 31;
    int idx = y*SPR + (x >> 3);
    int se = n*NSTRIP + idx;

    unsigned char hot = g_HOT[se];
    unsigned char nz  = g_NZ[se];
    if (!hot && !nz) return;

    float* __restrict__ Sn = g_S + n*IMG_SZ;
    const float* __restrict__ Tn = g_T + n*IMG_SZ;
    int lane = threadIdx.x & 31;

    bool myalive = false;
    if (hot && g_P[n*PIX + rem]) {
        float m = 0.f;
        #pragma unroll
        for (int dy = -1; dy <= 1; dy++) {
            int yy = y + dy;
            if ((unsigned)yy >= (unsigned)HH) continue;
            #pragma unroll
            for (int dx = -1; dx <= 1; dx++) {
                int xx = x + dx;
                if ((unsigned)xx >= (unsigned)WW) continue;
                m = fmaxf(m, Tn[yy*WW + xx]);
            }
        }
        myalive = m > THRESH;
    }
    unsigned bal = __ballot_sync(0xffffffffu, myalive);
    if (hot) {
        if (myalive) {
            #pragma unroll
            for (int c = 0; c < STATE; c++) Sn[c*PIX + rem] = Tn[c*PIX + rem];
        } else {
            #pragma unroll
            for (int c = 0; c < STATE; c++) Sn[c*PIX + rem] = 0.f;
        }
        if ((lane & 7) == 0)
            g_NZ[se] = ((bal >> (lane & 24)) & 0xFF) ? 1 : 0;
    } else {  // nz && !hot: strip dies (no pre-alive support)
        #pragma unroll
        for (int c = 0; c < STATE; c++) Sn[c*PIX + rem] = 0.f;
        if ((lane & 7) == 0) g_NZ[se] = 0;
    }
}

// ---------------- extract output ----------------
__global__ void k_extract(float* __restrict__ out)
{
    int g = blockIdx.x*256 + threadIdx.x;
    int n = g >> 10, rem = g & 1023;
    out[g] = g_S[n*IMG_SZ + rem];
}

// ---------------- launch ----------------
extern "C" void kernel_launch(void* const* d_in, const int* in_sizes, int n_in,
                              void* d_out, int out_size)
{
    const float* z   = (const float*)d_in[0];
    const float* w1  = (const float*)d_in[1];
    const float* b1  = (const float*)d_in[2];
    const float* w2  = (const float*)d_in[3];
    const float* b2  = (const float*)d_in[4];
    const float* wp  = (const float*)d_in[5];
    const float* bp  = (const float*)d_in[6];
    const float* wu1 = (const float*)d_in[7];
    const float* bu1 = (const float*)d_in[8];
    const float* wu2 = (const float*)d_in[9];
    const float* bu2 = (const float*)d_in[10];
    float* out = (float*)d_out;

    k_pack<<<(128*180 + 255)/256, 256>>>(wp, wu1);
    k_zero<<<(STATE_SZ + 255)/256, 256>>>();
    k_init<<<NB, 128>>>(z, w1, b1, w2, b2);

    for (int s = 0; s < STEPS; s++) {
        k_build<<<TOTSTRIP/256, 256>>>(s);
        k_step1<<<1024, 128>>>(s, bp, bu1, wu2, bu2);
        k_step2<<<(NB*PIX)/256, 256>>>();
    }
    k_extract<<<(NB*PIX)/256, 256>>>(out);
}